// round 3
// baseline (speedup 1.0000x reference)
#include <cuda_runtime.h>
#include <cuda_fp16.h>
#include <math.h>

#define NPL   80            // 5*16 planes
#define NYI   384
#define OSN   768
#define PAD   192
#define PLSZ  (768*768)
#define HALF_OUT ((size_t)NPL*NYI*NYI)

// fp16 complex scratch (two buffers, 189 MB each)
__device__ __half2 g_bufA[(size_t)NPL*OSN*OSN];
__device__ __half2 g_bufB[(size_t)NPL*OSN*OSN];
__device__ float2  g_twid[OSN];   // e^{-2*pi*i*j/768}

// W16^j = e^{-2*pi*i*j/16}, j = 0..9
__constant__ float2 c_w16[10] = {
    { 1.0f,            0.0f},
    { 0.9238795325f,  -0.3826834324f},
    { 0.7071067812f,  -0.7071067812f},
    { 0.3826834324f,  -0.9238795325f},
    { 0.0f,           -1.0f},
    {-0.3826834324f,  -0.9238795325f},
    {-0.7071067812f,  -0.7071067812f},
    {-0.9238795325f,  -0.3826834324f},
    {-1.0f,            0.0f},
    {-0.9238795325f,   0.3826834324f}
};

__device__ __forceinline__ float2 cmulf(float2 a, float2 b){
    return make_float2(a.x*b.x - a.y*b.y, a.x*b.y + a.y*b.x);
}
__device__ __forceinline__ float2 caddf(float2 a, float2 b){ return make_float2(a.x+b.x, a.y+b.y); }
__device__ __forceinline__ float2 csubf(float2 a, float2 b){ return make_float2(a.x-b.x, a.y-b.y); }

template<bool INV>
__device__ __forceinline__ float2 twmul(float2 a, float2 w){
    if (INV) w.y = -w.y;
    return cmulf(a, w);
}

__device__ __forceinline__ unsigned f2h(float2 v){
    __half2 h = __floats2half2_rn(v.x, v.y);
    return *reinterpret_cast<unsigned*>(&h);
}
__device__ __forceinline__ float2 h2f(unsigned u){
    __half2 h = *reinterpret_cast<__half2*>(&u);
    return __half22float2(h);
}

__global__ void k_twid(){
    int j = blockIdx.x*blockDim.x + threadIdx.x;
    if (j < OSN){
        double a = -2.0*3.14159265358979323846*(double)j/768.0;
        g_twid[j] = make_float2((float)cos(a), (float)sin(a));
    }
}

template<bool INV>
__device__ __forceinline__ void dft4(float2 &a0, float2 &a1, float2 &a2, float2 &a3){
    float2 t0=caddf(a0,a2), t1=csubf(a0,a2), t2=caddf(a1,a3), t3=csubf(a1,a3);
    a0 = caddf(t0,t2);  a2 = csubf(t0,t2);
    if (!INV){ a1 = make_float2(t1.x + t3.y, t1.y - t3.x);
               a3 = make_float2(t1.x - t3.y, t1.y + t3.x); }
    else     { a1 = make_float2(t1.x - t3.y, t1.y + t3.x);
               a3 = make_float2(t1.x + t3.y, t1.y - t3.x); }
}

// 16-point DFT in registers: 4x4 Cooley-Tukey. a[n] -> A[k] in place.
template<bool INV>
__device__ __forceinline__ void dft16(float2 a[16]){
    float2 b[16];
    #pragma unroll
    for (int n2 = 0; n2 < 4; ++n2){
        float2 x0=a[n2], x1=a[n2+4], x2=a[n2+8], x3=a[n2+12];
        dft4<INV>(x0,x1,x2,x3);
        b[0*4+n2]=x0; b[1*4+n2]=x1; b[2*4+n2]=x2; b[3*4+n2]=x3;
    }
    #pragma unroll
    for (int k1 = 0; k1 < 4; ++k1){
        float2 y0 = b[k1*4+0];
        float2 y1 = twmul<INV>(b[k1*4+1], c_w16[k1]);
        float2 y2 = twmul<INV>(b[k1*4+2], c_w16[2*k1]);
        float2 y3 = twmul<INV>(b[k1*4+3], c_w16[3*k1]);
        dft4<INV>(y0,y1,y2,y3);
        a[k1]=y0; a[k1+4]=y1; a[k1+8]=y2; a[k1+12]=y3;
    }
}

// 768-point Stockham FFT, radices [16,16,3], NBATCH interleaved batches.
// Layout: element j of batch col at buf[j*LD + col]. Result in returned buffer.
template<int NBATCH, int LD, bool INV>
__device__ float2* fft768_s(float2* s0, float2* s1, int tid, int nthr){
    // Stage A: l=1, R=16, m=48, twiddle-free
    for (int w = tid; w < 48*NBATCH; w += nthr){
        int col = w % NBATCH, idx = w / NBATCH;
        float2 a[16];
        #pragma unroll
        for (int r = 0; r < 16; ++r) a[r] = s0[(idx + 48*r)*LD + col];
        dft16<INV>(a);
        #pragma unroll
        for (int r = 0; r < 16; ++r) s1[(idx*16 + r)*LD + col] = a[r];
    }
    __syncthreads();
    // Stage B: l=16, R=16, m=48, twiddle index 3*r*k
    for (int w = tid; w < 48*NBATCH; w += nthr){
        int col = w % NBATCH, idx = w / NBATCH;
        int k = idx & 15, j = idx >> 4;
        float2 a[16];
        #pragma unroll
        for (int r = 0; r < 16; ++r) a[r] = s1[(idx + 48*r)*LD + col];
        #pragma unroll
        for (int r = 1; r < 16; ++r) a[r] = twmul<INV>(a[r], g_twid[3*r*k]);
        dft16<INV>(a);
        #pragma unroll
        for (int r = 0; r < 16; ++r) s0[(j*256 + k + 16*r)*LD + col] = a[r];
    }
    __syncthreads();
    // Stage C: l=256, R=3, m=256, twiddle index r*k
    for (int w = tid; w < 256*NBATCH; w += nthr){
        int col = w % NBATCH, k = w / NBATCH;
        float2 a0 = s0[(k      )*LD + col];
        float2 a1 = s0[(k + 256)*LD + col];
        float2 a2 = s0[(k + 512)*LD + col];
        a1 = twmul<INV>(a1, g_twid[k]);
        a2 = twmul<INV>(a2, g_twid[2*k]);
        float2 t = caddf(a1,a2);
        float2 d = csubf(a1,a2);
        float2 b0 = caddf(a0,t);
        float2 u  = make_float2(a0.x - 0.5f*t.x, a0.y - 0.5f*t.y);
        const float S = INV ? 0.86602540378443864676f : -0.86602540378443864676f;
        float2 b1 = make_float2(u.x - S*d.y, u.y + S*d.x);
        float2 b2 = make_float2(u.x + S*d.y, u.y - S*d.x);
        s1[(k      )*LD + col] = b0;
        s1[(k + 256)*LD + col] = b1;
        s1[(k + 512)*LD + col] = b2;
    }
    __syncthreads();
    return s1;
}

// K1: pad + input checkerboard + forward row FFT (384 nonzero rows, 4 rows/block)
__global__ void __launch_bounds__(256) k_row_fwd(const float* __restrict__ re,
                                                 const float* __restrict__ im){
    extern __shared__ float2 sm[];
    float2* s0 = sm; float2* s1 = sm + 768*5;
    int p = blockIdx.y, iy0 = blockIdx.x*4, tid = threadIdx.x;
    for (int w = tid; w < 4*768; w += 256){
        int r = w / 768, x = w - r*768;
        float2 v = make_float2(0.f, 0.f);
        if (x >= PAD && x < PAD + NYI){
            int ix = x - PAD, iy = iy0 + r;
            size_t o = ((size_t)p*NYI + iy)*NYI + ix;
            float s = ((iy + ix) & 1) ? -1.f : 1.f;
            v.x = s*re[o]; v.y = s*im[o];
        }
        s0[x*5 + r] = v;
    }
    __syncthreads();
    float2* o = fft768_s<4,5,false>(s0, s1, tid, 256);
    for (int w = tid; w < 4*768; w += 256){
        int r = w / 768, x = w - r*768;
        float2 v = o[x*5 + r];
        unsigned* dst = reinterpret_cast<unsigned*>(
            &g_bufA[((size_t)p*OSN + PAD + iy0 + r)*OSN + x]);
        *dst = f2h(v);
    }
}

// K2: forward column FFT (8 cols/block), pruned load of central 384 rows
__global__ void __launch_bounds__(384) k_col_fwd(){
    extern __shared__ float2 sm[];
    float2* s0 = sm; float2* s1 = sm + 768*9;
    int p = blockIdx.y, x0 = blockIdx.x*8, tid = threadIdx.x;
    for (int y = tid; y < 768; y += 384){
        float2 v[8];
        if (y >= PAD && y < PAD + NYI){
            const uint4* src = reinterpret_cast<const uint4*>(
                &g_bufA[((size_t)p*OSN + y)*OSN + x0]);
            uint4 u0 = src[0], u1 = src[1];
            v[0]=h2f(u0.x); v[1]=h2f(u0.y); v[2]=h2f(u0.z); v[3]=h2f(u0.w);
            v[4]=h2f(u1.x); v[5]=h2f(u1.y); v[6]=h2f(u1.z); v[7]=h2f(u1.w);
        } else {
            #pragma unroll
            for (int c = 0; c < 8; ++c) v[c] = make_float2(0.f, 0.f);
        }
        #pragma unroll
        for (int c = 0; c < 8; ++c) s0[y*9 + c] = v[c];
    }
    __syncthreads();
    float2* o = fft768_s<8,9,false>(s0, s1, tid, 384);
    for (int y = tid; y < 768; y += 384){
        uint4 u0, u1;
        u0.x=f2h(o[y*9+0]); u0.y=f2h(o[y*9+1]); u0.z=f2h(o[y*9+2]); u0.w=f2h(o[y*9+3]);
        u1.x=f2h(o[y*9+4]); u1.y=f2h(o[y*9+5]); u1.z=f2h(o[y*9+6]); u1.w=f2h(o[y*9+7]);
        uint4* dst = reinterpret_cast<uint4*>(&g_bufB[((size_t)p*OSN + y)*OSN + x0]);
        dst[0] = u0; dst[1] = u1;
    }
}

// K3: pointwise 5x5 complex subspace mixing across 16 coils (fp16 io, fp32 math).
// Normalization 1/768^2 folded into the kernel values here.
__global__ void __launch_bounds__(256) k_einsum(const float* __restrict__ kre,
                                                const float* __restrict__ kim){
    int px = blockIdx.x*256 + threadIdx.x;
    if (px >= PLSZ) return;
    const float sc = 1.0f/589824.0f;
    float2 kv[25];
    #pragma unroll
    for (int q = 0; q < 25; ++q)
        kv[q] = make_float2(sc*kre[(size_t)q*PLSZ + px], sc*kim[(size_t)q*PLSZ + px]);
    #pragma unroll 1
    for (int c = 0; c < 16; ++c){
        float2 vin[5];
        #pragma unroll
        for (int a = 0; a < 5; ++a)
            vin[a] = __half22float2(g_bufB[((size_t)(a*16 + c))*PLSZ + px]);
        #pragma unroll
        for (int b = 0; b < 5; ++b){
            float2 acc = make_float2(0.f, 0.f);
            #pragma unroll
            for (int a = 0; a < 5; ++a){
                float2 k2 = kv[b*5 + a];
                acc.x += k2.x*vin[a].x - k2.y*vin[a].y;
                acc.y += k2.x*vin[a].y + k2.y*vin[a].x;
            }
            g_bufA[((size_t)(b*16 + c))*PLSZ + px] = __floats2half2_rn(acc.x, acc.y);
        }
    }
}

// K4: inverse column FFT (8 cols/block), writes only central 384 rows
__global__ void __launch_bounds__(384) k_col_inv(){
    extern __shared__ float2 sm[];
    float2* s0 = sm; float2* s1 = sm + 768*9;
    int p = blockIdx.y, x0 = blockIdx.x*8, tid = threadIdx.x;
    for (int y = tid; y < 768; y += 384){
        const uint4* src = reinterpret_cast<const uint4*>(
            &g_bufA[((size_t)p*OSN + y)*OSN + x0]);
        uint4 u0 = src[0], u1 = src[1];
        s0[y*9+0]=h2f(u0.x); s0[y*9+1]=h2f(u0.y); s0[y*9+2]=h2f(u0.z); s0[y*9+3]=h2f(u0.w);
        s0[y*9+4]=h2f(u1.x); s0[y*9+5]=h2f(u1.y); s0[y*9+6]=h2f(u1.z); s0[y*9+7]=h2f(u1.w);
    }
    __syncthreads();
    float2* o = fft768_s<8,9,true>(s0, s1, tid, 384);
    for (int w = tid; w < NYI; w += 384){
        int y = PAD + w;
        uint4 u0, u1;
        u0.x=f2h(o[y*9+0]); u0.y=f2h(o[y*9+1]); u0.z=f2h(o[y*9+2]); u0.w=f2h(o[y*9+3]);
        u1.x=f2h(o[y*9+4]); u1.y=f2h(o[y*9+5]); u1.z=f2h(o[y*9+6]); u1.w=f2h(o[y*9+7]);
        uint4* dst = reinterpret_cast<uint4*>(&g_bufB[((size_t)p*OSN + y)*OSN + x0]);
        dst[0] = u0; dst[1] = u1;
    }
}

// K5: inverse row FFT (4 rows/block), crop + output checkerboard, fp32 out
__global__ void __launch_bounds__(256) k_row_inv(float* __restrict__ out){
    extern __shared__ float2 sm[];
    float2* s0 = sm; float2* s1 = sm + 768*5;
    int p = blockIdx.y, oy0 = blockIdx.x*4, tid = threadIdx.x;
    for (int w = tid; w < 4*768; w += 256){
        int r = w / 768, x = w - r*768;
        const unsigned* src = reinterpret_cast<const unsigned*>(
            &g_bufB[((size_t)p*OSN + PAD + oy0 + r)*OSN + x]);
        s0[x*5 + r] = h2f(*src);
    }
    __syncthreads();
    float2* o = fft768_s<4,5,true>(s0, s1, tid, 256);
    for (int w = tid; w < 4*NYI; w += 256){
        int r = w / NYI, ox = w - r*NYI;
        int oy = oy0 + r;
        float2 v = o[(PAD + ox)*5 + r];
        float s = ((oy + ox) & 1) ? -1.f : 1.f;
        size_t off = ((size_t)p*NYI + oy)*NYI + ox;
        out[off]            = s*v.x;
        out[off + HALF_OUT] = s*v.y;
    }
}

extern "C" void kernel_launch(void* const* d_in, const int* in_sizes, int n_in,
                              void* d_out, int out_size){
    const float* ire = (const float*)d_in[0];
    const float* iim = (const float*)d_in[1];
    const float* kre = (const float*)d_in[2];
    const float* kim = (const float*)d_in[3];
    float* out = (float*)d_out;

    const int SM_ROW = 2*768*5*sizeof(float2);   // 61440
    const int SM_COL = 2*768*9*sizeof(float2);   // 110592
    cudaFuncSetAttribute(k_row_fwd, cudaFuncAttributeMaxDynamicSharedMemorySize, SM_ROW);
    cudaFuncSetAttribute(k_row_inv, cudaFuncAttributeMaxDynamicSharedMemorySize, SM_ROW);
    cudaFuncSetAttribute(k_col_fwd, cudaFuncAttributeMaxDynamicSharedMemorySize, SM_COL);
    cudaFuncSetAttribute(k_col_inv, cudaFuncAttributeMaxDynamicSharedMemorySize, SM_COL);

    k_twid<<<3, 256>>>();

    k_row_fwd<<<dim3(96, NPL), 256, SM_ROW>>>(ire, iim);
    k_col_fwd<<<dim3(96, NPL), 384, SM_COL>>>();
    k_einsum<<<(PLSZ + 255)/256, 256>>>(kre, kim);
    k_col_inv<<<dim3(96, NPL), 384, SM_COL>>>();
    k_row_inv<<<dim3(96, NPL), 256, SM_ROW>>>(out);
}

// round 4
// speedup vs baseline: 1.0930x; 1.0930x over previous
#include <cuda_runtime.h>
#include <cuda_fp16.h>
#include <math.h>

#define NPL   80
#define NYI   384
#define OSN   768
#define PAD   192
#define PLSZ  (768*768)
#define HALF_OUT ((size_t)NPL*NYI*NYI)

// fp16 complex scratch
__device__ __half2 g_bufA[(size_t)NPL*OSN*OSN];
__device__ __half2 g_bufB[(size_t)NPL*OSN*OSN];
__device__ float2  g_twid[OSN];   // e^{-2*pi*i*j/768}

// Bank swizzle on float2-element index: bits2-4 ^= bits4-6 (bijective).
#define SWZ(e) ((e) ^ ((((e) >> 4) & 7) << 2))

__device__ __forceinline__ float2 cmulf(float2 a, float2 b){
    return make_float2(a.x*b.x - a.y*b.y, a.x*b.y + a.y*b.x);
}
__device__ __forceinline__ float2 caddf(float2 a, float2 b){ return make_float2(a.x+b.x, a.y+b.y); }
__device__ __forceinline__ float2 csubf(float2 a, float2 b){ return make_float2(a.x-b.x, a.y-b.y); }

template<bool INV>
__device__ __forceinline__ float2 twmul(float2 a, float2 w){
    if (INV) w.y = -w.y;
    return cmulf(a, w);
}

__device__ __forceinline__ unsigned f2h(float2 v){
    __half2 h = __floats2half2_rn(v.x, v.y);
    return *reinterpret_cast<unsigned*>(&h);
}
__device__ __forceinline__ float2 h2f(unsigned u){
    __half2 h = *reinterpret_cast<__half2*>(&u);
    return __half22float2(h);
}

__global__ void k_twid(){
    int j = blockIdx.x*blockDim.x + threadIdx.x;
    if (j < OSN){
        double a = -2.0*3.14159265358979323846*(double)j/768.0;
        g_twid[j] = make_float2((float)cos(a), (float)sin(a));
    }
}

// 768-pt Stockham FFT, radices [4,4,4,4,3], 4 interleaved batches (e = idx*4+col),
// swizzled double-buffer smem. 256 threads. Result in returned buffer.
template<bool INV>
__device__ float2* fft768_4(float2* s0, float2* s1, int tid){
    float2* in  = s0;
    float2* out = s1;
    int l = 1;
    #pragma unroll
    for (int st = 0; st < 4; ++st){
        const int m = 192;
        int step = 192 / l;
        #pragma unroll 1
        for (int w = tid; w < 768; w += 256){
            int col = w & 3, idx = w >> 2;
            int k = idx % l, j = idx / l;
            float2 a0 = in[SWZ((idx      )*4 + col)];
            float2 a1 = in[SWZ((idx +   m)*4 + col)];
            float2 a2 = in[SWZ((idx + 2*m)*4 + col)];
            float2 a3 = in[SWZ((idx + 3*m)*4 + col)];
            float2 w1 = g_twid[k*step];
            if (INV) w1.y = -w1.y;
            float2 w2 = cmulf(w1, w1);
            float2 w3 = cmulf(w2, w1);
            a1 = cmulf(a1, w1);
            a2 = cmulf(a2, w2);
            a3 = cmulf(a3, w3);
            float2 t0 = caddf(a0, a2), t1 = csubf(a0, a2);
            float2 t2 = caddf(a1, a3), t3 = csubf(a1, a3);
            float2 b0 = caddf(t0, t2);
            float2 b2 = csubf(t0, t2);
            float2 b1, b3;
            if (!INV){ b1 = make_float2(t1.x + t3.y, t1.y - t3.x);
                       b3 = make_float2(t1.x - t3.y, t1.y + t3.x); }
            else     { b1 = make_float2(t1.x - t3.y, t1.y + t3.x);
                       b3 = make_float2(t1.x + t3.y, t1.y - t3.x); }
            int ob = j*4*l + k;
            out[SWZ((ob      )*4 + col)] = b0;
            out[SWZ((ob +   l)*4 + col)] = b1;
            out[SWZ((ob + 2*l)*4 + col)] = b2;
            out[SWZ((ob + 3*l)*4 + col)] = b3;
        }
        __syncthreads();
        float2* t = in; in = out; out = t;
        l *= 4;
    }
    // radix-3: l=256
    #pragma unroll 1
    for (int w = tid; w < 1024; w += 256){
        int col = w & 3, k = w >> 2;
        float2 a0 = in[SWZ((k      )*4 + col)];
        float2 a1 = in[SWZ((k + 256)*4 + col)];
        float2 a2 = in[SWZ((k + 512)*4 + col)];
        a1 = twmul<INV>(a1, g_twid[k]);
        a2 = twmul<INV>(a2, g_twid[2*k]);
        float2 t = caddf(a1, a2);
        float2 d = csubf(a1, a2);
        float2 b0 = caddf(a0, t);
        float2 u  = make_float2(a0.x - 0.5f*t.x, a0.y - 0.5f*t.y);
        const float S = INV ? 0.86602540378443864676f : -0.86602540378443864676f;
        float2 b1 = make_float2(u.x - S*d.y, u.y + S*d.x);
        float2 b2 = make_float2(u.x + S*d.y, u.y - S*d.x);
        out[SWZ((k      )*4 + col)] = b0;
        out[SWZ((k + 256)*4 + col)] = b1;
        out[SWZ((k + 512)*4 + col)] = b2;
    }
    __syncthreads();
    return out;
}

// K1: pad + checkerboard + forward row FFT (4 rows/block)
__global__ void __launch_bounds__(256) k_row_fwd(const float* __restrict__ re,
                                                 const float* __restrict__ im){
    extern __shared__ float2 sm[];
    float2* s0 = sm; float2* s1 = sm + 768*4;
    int p = blockIdx.y, iy0 = blockIdx.x*4, tid = threadIdx.x;
    #pragma unroll 1
    for (int w = tid; w < 3072; w += 256){
        int x = w >> 2, r = w & 3;
        float2 v = make_float2(0.f, 0.f);
        if (x >= PAD && x < PAD + NYI){
            int ix = x - PAD, iy = iy0 + r;
            size_t o = ((size_t)p*NYI + iy)*NYI + ix;
            float s = ((iy + ix) & 1) ? -1.f : 1.f;
            v.x = s*re[o]; v.y = s*im[o];
        }
        s0[SWZ(x*4 + r)] = v;
    }
    __syncthreads();
    float2* o = fft768_4<false>(s0, s1, tid);
    #pragma unroll 1
    for (int w = tid; w < 3072; w += 256){
        int x = w >> 2, r = w & 3;
        unsigned* dst = reinterpret_cast<unsigned*>(
            &g_bufA[((size_t)p*OSN + PAD + iy0 + r)*OSN + x]);
        *dst = f2h(o[SWZ(x*4 + r)]);
    }
}

// K2: forward column FFT (4 cols/block), pruned load of central 384 rows
__global__ void __launch_bounds__(256) k_col_fwd(){
    extern __shared__ float2 sm[];
    float2* s0 = sm; float2* s1 = sm + 768*4;
    int p = blockIdx.y, x0 = blockIdx.x*4, tid = threadIdx.x;
    #pragma unroll 1
    for (int y = tid; y < 768; y += 256){
        float2 v[4];
        if (y >= PAD && y < PAD + NYI){
            uint4 u = *reinterpret_cast<const uint4*>(
                &g_bufA[((size_t)p*OSN + y)*OSN + x0]);
            v[0]=h2f(u.x); v[1]=h2f(u.y); v[2]=h2f(u.z); v[3]=h2f(u.w);
        } else {
            #pragma unroll
            for (int c = 0; c < 4; ++c) v[c] = make_float2(0.f, 0.f);
        }
        #pragma unroll
        for (int c = 0; c < 4; ++c) s0[SWZ(y*4 + c)] = v[c];
    }
    __syncthreads();
    float2* o = fft768_4<false>(s0, s1, tid);
    #pragma unroll 1
    for (int y = tid; y < 768; y += 256){
        uint4 u;
        u.x = f2h(o[SWZ(y*4+0)]); u.y = f2h(o[SWZ(y*4+1)]);
        u.z = f2h(o[SWZ(y*4+2)]); u.w = f2h(o[SWZ(y*4+3)]);
        *reinterpret_cast<uint4*>(&g_bufB[((size_t)p*OSN + y)*OSN + x0]) = u;
    }
}

// K3: pointwise 5x5 complex subspace mixing across 16 coils, fp16 io / fp32 math.
__global__ void __launch_bounds__(256) k_einsum(const float* __restrict__ kre,
                                                const float* __restrict__ kim){
    int px = blockIdx.x*256 + threadIdx.x;
    if (px >= PLSZ) return;
    const float sc = 1.0f/589824.0f;
    float2 kv[25];
    #pragma unroll
    for (int q = 0; q < 25; ++q)
        kv[q] = make_float2(sc*kre[(size_t)q*PLSZ + px], sc*kim[(size_t)q*PLSZ + px]);
    #pragma unroll 1
    for (int c = 0; c < 16; ++c){
        float2 vin[5];
        #pragma unroll
        for (int a = 0; a < 5; ++a)
            vin[a] = __half22float2(g_bufB[((size_t)(a*16 + c))*PLSZ + px]);
        #pragma unroll
        for (int b = 0; b < 5; ++b){
            float2 acc = make_float2(0.f, 0.f);
            #pragma unroll
            for (int a = 0; a < 5; ++a){
                float2 k2 = kv[b*5 + a];
                acc.x += k2.x*vin[a].x - k2.y*vin[a].y;
                acc.y += k2.x*vin[a].y + k2.y*vin[a].x;
            }
            g_bufA[((size_t)(b*16 + c))*PLSZ + px] = __floats2half2_rn(acc.x, acc.y);
        }
    }
}

// K4: inverse column FFT (4 cols/block), writes only central 384 rows
__global__ void __launch_bounds__(256) k_col_inv(){
    extern __shared__ float2 sm[];
    float2* s0 = sm; float2* s1 = sm + 768*4;
    int p = blockIdx.y, x0 = blockIdx.x*4, tid = threadIdx.x;
    #pragma unroll 1
    for (int y = tid; y < 768; y += 256){
        uint4 u = *reinterpret_cast<const uint4*>(
            &g_bufA[((size_t)p*OSN + y)*OSN + x0]);
        s0[SWZ(y*4+0)] = h2f(u.x); s0[SWZ(y*4+1)] = h2f(u.y);
        s0[SWZ(y*4+2)] = h2f(u.z); s0[SWZ(y*4+3)] = h2f(u.w);
    }
    __syncthreads();
    float2* o = fft768_4<true>(s0, s1, tid);
    #pragma unroll 1
    for (int w = tid; w < NYI; w += 256){
        int y = PAD + w;
        uint4 u;
        u.x = f2h(o[SWZ(y*4+0)]); u.y = f2h(o[SWZ(y*4+1)]);
        u.z = f2h(o[SWZ(y*4+2)]); u.w = f2h(o[SWZ(y*4+3)]);
        *reinterpret_cast<uint4*>(&g_bufB[((size_t)p*OSN + y)*OSN + x0]) = u;
    }
}

// K5: inverse row FFT (4 rows/block), crop + output checkerboard, fp32 out
__global__ void __launch_bounds__(256) k_row_inv(float* __restrict__ out){
    extern __shared__ float2 sm[];
    float2* s0 = sm; float2* s1 = sm + 768*4;
    int p = blockIdx.y, oy0 = blockIdx.x*4, tid = threadIdx.x;
    #pragma unroll 1
    for (int w = tid; w < 3072; w += 256){
        int x = w >> 2, r = w & 3;
        const unsigned* src = reinterpret_cast<const unsigned*>(
            &g_bufB[((size_t)p*OSN + PAD + oy0 + r)*OSN + x]);
        s0[SWZ(x*4 + r)] = h2f(*src);
    }
    __syncthreads();
    float2* o = fft768_4<true>(s0, s1, tid);
    #pragma unroll 1
    for (int w = tid; w < 4*NYI; w += 256){
        int ox = w >> 2, r = w & 3;
        int oy = oy0 + r;
        float2 v = o[SWZ((PAD + ox)*4 + r)];
        float s = ((oy + ox) & 1) ? -1.f : 1.f;
        size_t off = ((size_t)p*NYI + oy)*NYI + ox;
        out[off]            = s*v.x;
        out[off + HALF_OUT] = s*v.y;
    }
}

extern "C" void kernel_launch(void* const* d_in, const int* in_sizes, int n_in,
                              void* d_out, int out_size){
    const float* ire = (const float*)d_in[0];
    const float* iim = (const float*)d_in[1];
    const float* kre = (const float*)d_in[2];
    const float* kim = (const float*)d_in[3];
    float* out = (float*)d_out;

    const int SM_FFT = 2*768*4*sizeof(float2);   // 49152
    cudaFuncSetAttribute(k_row_fwd, cudaFuncAttributeMaxDynamicSharedMemorySize, SM_FFT);
    cudaFuncSetAttribute(k_row_inv, cudaFuncAttributeMaxDynamicSharedMemorySize, SM_FFT);
    cudaFuncSetAttribute(k_col_fwd, cudaFuncAttributeMaxDynamicSharedMemorySize, SM_FFT);
    cudaFuncSetAttribute(k_col_inv, cudaFuncAttributeMaxDynamicSharedMemorySize, SM_FFT);

    k_twid<<<3, 256>>>();

    k_row_fwd<<<dim3(96, NPL), 256, SM_FFT>>>(ire, iim);
    k_col_fwd<<<dim3(192, NPL), 256, SM_FFT>>>();
    k_einsum<<<(PLSZ + 255)/256, 256>>>(kre, kim);
    k_col_inv<<<dim3(192, NPL), 256, SM_FFT>>>();
    k_row_inv<<<dim3(96, NPL), 256, SM_FFT>>>(out);
}